// round 10
// baseline (speedup 1.0000x reference)
#include <cuda_runtime.h>
#include <cstdint>

#define NQ_CAP 20480          // 256 * 80 for the fused scan
#define E_CAP  640000
#define DF     128
#define LDA2   132            // padded row stride (words) -> conflict-free frags

// ---------------- static device scratch -------------------------------------
__device__ int      g_counts [NQ_CAP];
__device__ int      g_cursor [NQ_CAP];
__device__ int      g_eids   [E_CAP];
__device__ int      g_erow   [E_CAP];
__device__ float    g_agg    [(size_t)NQ_CAP * DF];
__device__ float    g_P      [(size_t)NQ_CAP * DF];   // h_q @ We1_top + b1
__device__ float    g_Q      [(size_t)NQ_CAP * DF];   // h_kv @ We1_bot
__device__ uint2    g_w1tp[8192];   // packed tf32 frag pairs: [ks][tg][n]
__device__ uint2    g_w1bp[8192];
__device__ uint2    g_w2ep[8192];
__device__ uint32_t g_w1n[256 * 128];
__device__ uint32_t g_w2n[128 * 128];
__device__ unsigned long long g_barv = 0;   // monotonic grid-barrier counter

// ---------------- helpers ---------------------------------------------------
__device__ __forceinline__ uint32_t f2tf(float x) {
    uint32_t u; asm("cvt.rna.tf32.f32 %0, %1;" : "=r"(u) : "f"(x)); return u;
}
__device__ __forceinline__ float silu(float x) {
    // fast-path: MUFU.EX2 + MUFU.RCP regardless of -use_fast_math
    return __fdividef(x, 1.0f + __expf(-x));
}
__device__ __forceinline__ void mma8(float c[4], const uint32_t a[4],
                                     uint32_t b0, uint32_t b1) {
    asm("mma.sync.aligned.m16n8k8.row.col.f32.tf32.tf32.f32 "
        "{%0,%1,%2,%3}, {%4,%5,%6,%7}, {%8,%9}, {%0,%1,%2,%3};"
        : "+f"(c[0]), "+f"(c[1]), "+f"(c[2]), "+f"(c[3])
        : "r"(a[0]), "r"(a[1]), "r"(a[2]), "r"(a[3]), "r"(b0), "r"(b1));
}

// Monotonic-counter grid barrier (all blocks co-resident; graph-replay safe).
__device__ __forceinline__ void gbar(int nb) {
    __syncthreads();
    __threadfence();
    if (threadIdx.x == 0) {
        unsigned long long old = atomicAdd(&g_barv, 1ULL);
        unsigned long long target = (old / (unsigned long long)nb + 1ULL) *
                                    (unsigned long long)nb;
        unsigned long long v;
        do {
            asm volatile("ld.global.acquire.gpu.u64 %0, [%1];"
                         : "=l"(v) : "l"(&g_barv));
        } while (v < target);
    }
    __syncthreads();
}

// ---------------- fused CSR kernel: pack + zero + hist | scan | scatter -----
__global__ void __launch_bounds__(256, 1)
csr_kernel(const float* __restrict__ We1, const float* __restrict__ We2,
           const float* __restrict__ Wn1, const float* __restrict__ Wn2,
           const int* __restrict__ ei, int E, int nq) {
    int nb = gridDim.x;
    int gt = blockIdx.x * 256 + threadIdx.x;
    int gstride = nb * 256;

    // ---- phase A: weight packing + zeroing + histogram ----
    for (int i = gt; i < 49152; i += gstride) {
        if (i < 8192) {
            int ks = i >> 9, tg = (i >> 7) & 3, n = i & 127;
            int k0 = ks * 8 + tg;
            g_w1tp[i] = make_uint2(f2tf(We1[k0 * 128 + n]),         f2tf(We1[(k0 + 4) * 128 + n]));
            g_w1bp[i] = make_uint2(f2tf(We1[(128 + k0) * 128 + n]), f2tf(We1[(132 + k0) * 128 + n]));
            g_w2ep[i] = make_uint2(f2tf(We2[k0 * 128 + n]),         f2tf(We2[(k0 + 4) * 128 + n]));
        }
        if (i < 32768) g_w1n[i] = f2tf(Wn1[i]);
        else           g_w2n[i - 32768] = f2tf(Wn2[i - 32768]);
    }
    for (int i = gt; i < NQ_CAP; i += gstride) g_counts[i] = 0;
    int nagg = nq * DF;
    for (int i = gt; i < nagg; i += gstride) g_agg[i] = 0.f;
    gbar(nb);
    for (int e = gt; e < E; e += gstride) atomicAdd(&g_counts[ei[e]], 1);
    gbar(nb);

    // ---- phase B: exclusive scan (block 0 only; 256 thr x 80 elems) ----
    if (blockIdx.x == 0) {
        __shared__ int wt[8];
        int tid = threadIdx.x, lane = tid & 31, w = tid >> 5;
        int base = tid * 80;
        int s = 0;
        for (int i = 0; i < 80; i++) s += g_counts[base + i];
        int v = s;
#pragma unroll
        for (int o = 1; o < 32; o <<= 1) {
            int t = __shfl_up_sync(~0u, v, o); if (lane >= o) v += t;
        }
        if (lane == 31) wt[w] = v;
        __syncthreads();
        if (w == 0 && lane < 8) {
            int x = wt[lane];
#pragma unroll
            for (int o = 1; o < 8; o <<= 1) {
                int t = __shfl_up_sync(0xFFu, x, o); if (lane >= o) x += t;
            }
            wt[lane] = x;
        }
        __syncthreads();
        int ex = v + (w ? wt[w - 1] : 0) - s;
        for (int i = 0; i < 80; i++) {
            int c = g_counts[base + i];
            g_cursor[base + i] = ex;
            ex += c;
        }
    }
    gbar(nb);

    // ---- phase C: scatter (CSR-sorted edge ids) ----
    for (int e = gt; e < E; e += gstride) {
        int r = ei[e];
        int pos = atomicAdd(&g_cursor[r], 1);
        g_eids[pos] = e; g_erow[pos] = r;
    }
}

// ---------------- single-layer GEMM: P/Q precompute -------------------------
template <int SEL>
__global__ void __launch_bounds__(256, 2)
pq_kernel(const float* __restrict__ src, const float* __restrict__ bias, int nrows) {
    const uint2* __restrict__ Wp = (SEL == 0) ? g_w1tp : g_w1bp;
    float* __restrict__ dst      = (SEL == 0) ? g_P    : g_Q;
    extern __shared__ uint32_t As[];          // [128][LDA2]
    int tid = threadIdx.x;
    {
        int r = tid >> 1, half = tid & 1;
        int rowg = blockIdx.x * 128 + r;
        bool ok = rowg < nrows;
        const float4* s4 = (const float4*)(src + (size_t)(ok ? rowg : 0) * DF + half * 64);
#pragma unroll
        for (int j = 0; j < 16; j++) {
            float4 v = ok ? s4[j] : make_float4(0.f, 0.f, 0.f, 0.f);
            uint4 u; u.x = f2tf(v.x); u.y = f2tf(v.y); u.z = f2tf(v.z); u.w = f2tf(v.w);
            *(uint4*)&As[r * LDA2 + half * 64 + j * 4] = u;
        }
    }
    __syncthreads();

    int lane = tid & 31, wid = tid >> 5, gid = lane >> 2, tg = lane & 3;
    float acc[8][2][4];
#pragma unroll
    for (int nt = 0; nt < 2; nt++) {
        int col = wid * 16 + nt * 8 + tg * 2;
        float b0 = (SEL == 0) ? bias[col] : 0.f;
        float b1 = (SEL == 0) ? bias[col + 1] : 0.f;
#pragma unroll
        for (int mt = 0; mt < 8; mt++) {
            acc[mt][nt][0] = b0; acc[mt][nt][1] = b1;
            acc[mt][nt][2] = b0; acc[mt][nt][3] = b1;
        }
    }
#pragma unroll
    for (int ks = 0; ks < 16; ks++) {
        uint2 b0 = Wp[(ks * 4 + tg) * 128 + wid * 16 + gid];
        uint2 b1 = Wp[(ks * 4 + tg) * 128 + wid * 16 + 8 + gid];
#pragma unroll
        for (int mt = 0; mt < 8; mt++) {
            uint32_t a[4];
            const uint32_t* ap = As + (mt * 16 + gid) * LDA2 + ks * 8 + tg;
            a[0] = ap[0]; a[1] = ap[8 * LDA2]; a[2] = ap[4]; a[3] = ap[8 * LDA2 + 4];
            mma8(acc[mt][0], a, b0.x, b0.y);
            mma8(acc[mt][1], a, b1.x, b1.y);
        }
    }
#pragma unroll
    for (int mt = 0; mt < 8; mt++) {
        int r0 = blockIdx.x * 128 + mt * 16 + gid, r1 = r0 + 8;
#pragma unroll
        for (int nt = 0; nt < 2; nt++) {
            int col = wid * 16 + nt * 8 + tg * 2;
            if (r0 < nrows) {
                dst[(size_t)r0 * DF + col] = acc[mt][nt][0];
                dst[(size_t)r0 * DF + col + 1] = acc[mt][nt][1];
            }
            if (r1 < nrows) {
                dst[(size_t)r1 * DF + col] = acc[mt][nt][2];
                dst[(size_t)r1 * DF + col + 1] = acc[mt][nt][3];
            }
        }
    }
}

// ---------------- edge layer-2: 64-edge tiles, occupancy 3 ------------------
#define SMEM_E ((64 * LDA2 + 128) * 4)

__global__ void __launch_bounds__(256, 3)
edge_l2_kernel(const int* __restrict__ ei, int E,
               const float* __restrict__ b2, float* __restrict__ out_m) {
    extern __shared__ uint32_t S[];
    uint32_t* As = S;                         // [64][LDA2] tf32 H tile
    float*    Rb = (float*)S;                 // reused fp32 out staging
    int* s_eid = (int*)(S + 64 * LDA2);
    int* s_row = (int*)(S + 64 * LDA2 + 64);
    int tid = threadIdx.x;

    // ---- gather & build H = silu(P[row] + Q[col]) as tf32 ----
    {
        int r = tid >> 2, q = tid & 3;        // 64 rows x 4 threads/row
        int ci = blockIdx.x * 64 + r;
        int eid = -1, row = 0, col = 0;
        if (ci < E) { eid = g_eids[ci]; row = g_erow[ci]; col = ei[E + eid]; }
        if (q == 0) { s_eid[r] = eid; s_row[r] = (eid >= 0) ? row : -1; }
        const float4* p4 = (const float4*)(g_P + (size_t)row * DF + q * 32);
        const float4* q4 = (const float4*)(g_Q + (size_t)col * DF + q * 32);
#pragma unroll
        for (int j = 0; j < 8; j++) {
            float4 p = (eid >= 0) ? p4[j] : make_float4(0.f, 0.f, 0.f, 0.f);
            float4 qq = (eid >= 0) ? q4[j] : make_float4(0.f, 0.f, 0.f, 0.f);
            uint4 u;
            u.x = f2tf(silu(p.x + qq.x)); u.y = f2tf(silu(p.y + qq.y));
            u.z = f2tf(silu(p.z + qq.z)); u.w = f2tf(silu(p.w + qq.w));
            *(uint4*)&As[r * LDA2 + q * 32 + j * 4] = u;
        }
    }
    __syncthreads();

    int lane = tid & 31, wid = tid >> 5, gid = lane >> 2, tg = lane & 3;
    float acc[4][2][4];
#pragma unroll
    for (int nt = 0; nt < 2; nt++) {
        int col = wid * 16 + nt * 8 + tg * 2;
        float b0 = b2[col], b1 = b2[col + 1];
#pragma unroll
        for (int mt = 0; mt < 4; mt++) {
            acc[mt][nt][0] = b0; acc[mt][nt][1] = b1;
            acc[mt][nt][2] = b0; acc[mt][nt][3] = b1;
        }
    }
#pragma unroll
    for (int ks = 0; ks < 16; ks++) {
        uint2 b0 = g_w2ep[(ks * 4 + tg) * 128 + wid * 16 + gid];
        uint2 b1 = g_w2ep[(ks * 4 + tg) * 128 + wid * 16 + 8 + gid];
#pragma unroll
        for (int mt = 0; mt < 4; mt++) {
            uint32_t a[4];
            const uint32_t* ap = As + (mt * 16 + gid) * LDA2 + ks * 8 + tg;
            a[0] = ap[0]; a[1] = ap[8 * LDA2]; a[2] = ap[4]; a[3] = ap[8 * LDA2 + 4];
            mma8(acc[mt][0], a, b0.x, b0.y);
            mma8(acc[mt][1], a, b1.x, b1.y);
        }
    }
    __syncthreads();   // all warps done reading As -> safe to overwrite with Rb

    // ---- silu -> Rb (fp32) ----
#pragma unroll
    for (int mt = 0; mt < 4; mt++) {
        int r0 = mt * 16 + gid, r1 = r0 + 8;
#pragma unroll
        for (int nt = 0; nt < 2; nt++) {
            int col = wid * 16 + nt * 8 + tg * 2;
            Rb[r0 * LDA2 + col]     = silu(acc[mt][nt][0]);
            Rb[r0 * LDA2 + col + 1] = silu(acc[mt][nt][1]);
            Rb[r1 * LDA2 + col]     = silu(acc[mt][nt][2]);
            Rb[r1 * LDA2 + col + 1] = silu(acc[mt][nt][3]);
        }
    }
    __syncthreads();

    // ---- coalesced mij store ----
#pragma unroll
    for (int rep = 0; rep < 8; rep++) {
        int i = tid + rep * 256;               // 2048 float4 = 64 rows x 32
        int row = i >> 5, c4 = i & 31;
        int eid = s_eid[row];
        if (eid >= 0)
            *(float4*)(out_m + (size_t)eid * DF + c4 * 4) = *(float4*)&Rb[row * LDA2 + c4 * 4];
    }

    // ---- fused segmented aggregation (CSR-sorted rows) ----
    {
        int col = tid & 127, half = tid >> 7;
        int cur = -1; float racc = 0.f;
#pragma unroll 4
        for (int r0 = 0; r0 < 32; r0++) {
            int r = half * 32 + r0;
            int rw = s_row[r];
            if (rw != cur) {
                if (cur >= 0) atomicAdd(&g_agg[(size_t)cur * DF + col], racc);
                cur = rw; racc = 0.f;
            }
            if (rw >= 0) racc += Rb[r * LDA2 + col];
        }
        if (cur >= 0) atomicAdd(&g_agg[(size_t)cur * DF + col], racc);
    }
}

// ---------------- node MLP (proven path) ------------------------------------
#define LDA 260
#define SMEM_N (128 * LDA * 4)

__device__ __forceinline__ void mma_tiles(const uint32_t* __restrict__ As,
                                          const uint32_t* __restrict__ Bw,
                                          int ksteps, float acc[2][8][4],
                                          int warp_m, int warp_n, int gid, int tg) {
    for (int ks = 0; ks < ksteps; ks++) {
        int k0 = ks * 8;
        uint32_t a[2][4];
#pragma unroll
        for (int mt = 0; mt < 2; mt++) {
            const uint32_t* ap = As + (warp_m * 32 + mt * 16 + gid) * LDA + k0 + tg;
            a[mt][0] = ap[0]; a[mt][1] = ap[8 * LDA];
            a[mt][2] = ap[4]; a[mt][3] = ap[8 * LDA + 4];
        }
#pragma unroll
        for (int nt = 0; nt < 8; nt++) {
            int n = warp_n * 64 + nt * 8 + gid;
            uint32_t b0 = Bw[(k0 + tg) * 128 + n];
            uint32_t b1 = Bw[(k0 + tg + 4) * 128 + n];
#pragma unroll
            for (int mt = 0; mt < 2; mt++) mma8(acc[mt][nt], a[mt], b0, b1);
        }
    }
}
__global__ void __launch_bounds__(256, 1)
node_kernel(const float* __restrict__ Aq,
            const float* __restrict__ bias1, const float* __restrict__ bias2,
            float* __restrict__ outp, int nrows) {
    extern __shared__ uint32_t As[];
    int tid = threadIdx.x;
    {
        int r = tid >> 1, half = tid & 1;
        int rowg = blockIdx.x * 128 + r;
        bool ok = rowg < nrows;
        int n = ok ? rowg : 0;
        const float4* src = half ? (const float4*)(g_agg + (size_t)n * DF)
                                 : (const float4*)(Aq + (size_t)n * DF);
#pragma unroll
        for (int j = 0; j < 32; j++) {
            float4 v = ok ? src[j] : make_float4(0.f, 0.f, 0.f, 0.f);
            uint4 u; u.x = f2tf(v.x); u.y = f2tf(v.y); u.z = f2tf(v.z); u.w = f2tf(v.w);
            *(uint4*)&As[r * LDA + (half * 32 + j) * 4] = u;
        }
    }
    __syncthreads();
    int lane = tid & 31, wid = tid >> 5;
    int warp_m = wid >> 1, warp_n = wid & 1;
    int gid = lane >> 2, tg = lane & 3;

    float acc[2][8][4];
#pragma unroll
    for (int nt = 0; nt < 8; nt++) {
        int col = warp_n * 64 + nt * 8 + tg * 2;
        float b0 = bias1[col], b1 = bias1[col + 1];
#pragma unroll
        for (int mt = 0; mt < 2; mt++) {
            acc[mt][nt][0] = b0; acc[mt][nt][1] = b1;
            acc[mt][nt][2] = b0; acc[mt][nt][3] = b1;
        }
    }
    mma_tiles(As, g_w1n, 32, acc, warp_m, warp_n, gid, tg);
    __syncthreads();
#pragma unroll
    for (int mt = 0; mt < 2; mt++) {
        int row = warp_m * 32 + mt * 16 + gid;
#pragma unroll
        for (int nt = 0; nt < 8; nt++) {
            int col = warp_n * 64 + nt * 8 + tg * 2;
            As[row * LDA + col]           = f2tf(silu(acc[mt][nt][0]));
            As[row * LDA + col + 1]       = f2tf(silu(acc[mt][nt][1]));
            As[(row + 8) * LDA + col]     = f2tf(silu(acc[mt][nt][2]));
            As[(row + 8) * LDA + col + 1] = f2tf(silu(acc[mt][nt][3]));
        }
    }
    __syncthreads();
#pragma unroll
    for (int nt = 0; nt < 8; nt++) {
        int col = warp_n * 64 + nt * 8 + tg * 2;
        float b0 = bias2[col], b1 = bias2[col + 1];
#pragma unroll
        for (int mt = 0; mt < 2; mt++) {
            acc[mt][nt][0] = b0; acc[mt][nt][1] = b1;
            acc[mt][nt][2] = b0; acc[mt][nt][3] = b1;
        }
    }
    mma_tiles(As, g_w2n, 16, acc, warp_m, warp_n, gid, tg);
#pragma unroll
    for (int mt = 0; mt < 2; mt++) {
        int row = warp_m * 32 + mt * 16 + gid;
        int rg0 = blockIdx.x * 128 + row, rg1 = rg0 + 8;
#pragma unroll
        for (int nt = 0; nt < 8; nt++) {
            int col = warp_n * 64 + nt * 8 + tg * 2;
            if (rg0 < nrows) {
                const float* h = Aq + (size_t)rg0 * DF + col;
                float* o = outp + (size_t)rg0 * DF + col;
                o[0] = acc[mt][nt][0] + h[0]; o[1] = acc[mt][nt][1] + h[1];
            }
            if (rg1 < nrows) {
                const float* h = Aq + (size_t)rg1 * DF + col;
                float* o = outp + (size_t)rg1 * DF + col;
                o[0] = acc[mt][nt][2] + h[0]; o[1] = acc[mt][nt][3] + h[1];
            }
        }
    }
}

// ---------------- launch ----------------------------------------------------
extern "C" void kernel_launch(void* const* d_in, const int* in_sizes, int n_in,
                              void* d_out, int out_size) {
    const float* h_q  = (const float*)d_in[0];
    const float* h_kv = (const float*)d_in[1];
    const int*   ei   = (const int*)d_in[2];
    const float* We1  = (const float*)d_in[3];
    const float* be1  = (const float*)d_in[4];
    const float* We2  = (const float*)d_in[5];
    const float* be2  = (const float*)d_in[6];
    const float* Wn1  = (const float*)d_in[7];
    const float* bn1  = (const float*)d_in[8];
    const float* Wn2  = (const float*)d_in[9];
    const float* bn2  = (const float*)d_in[10];

    int nq  = in_sizes[0] / DF;
    int nkv = in_sizes[1] / DF;
    int E   = in_sizes[2] / 2;

    float* out_h = (float*)d_out;
    float* out_m = (float*)d_out + (size_t)nq * DF;

    static int nsm = 0;
    if (!nsm) cudaDeviceGetAttribute(&nsm, cudaDevAttrMultiProcessorCount, 0);

    const int PQ_SMEM = 128 * LDA2 * 4;
    cudaFuncSetAttribute(pq_kernel<0>,   cudaFuncAttributeMaxDynamicSharedMemorySize, PQ_SMEM);
    cudaFuncSetAttribute(pq_kernel<1>,   cudaFuncAttributeMaxDynamicSharedMemorySize, PQ_SMEM);
    cudaFuncSetAttribute(edge_l2_kernel, cudaFuncAttributeMaxDynamicSharedMemorySize, SMEM_E);
    cudaFuncSetAttribute(node_kernel,    cudaFuncAttributeMaxDynamicSharedMemorySize, SMEM_N);

    // Launch order: csr(1), pq0(2), pq1(3), edge(4) <- ncu captures the 4th
    csr_kernel<<<nsm, 256>>>(We1, We2, Wn1, Wn2, ei, E, nq);
    pq_kernel<0><<<(nq + 127) / 128, 256, PQ_SMEM>>>(h_q, be1, nq);
    pq_kernel<1><<<(nkv + 127) / 128, 256, PQ_SMEM>>>(h_kv, be1, nkv);
    edge_l2_kernel<<<(E + 63) / 64, 256, SMEM_E>>>(ei, E, be2, out_m);
    node_kernel<<<(nq + 127) / 128, 256, SMEM_N>>>(h_q, bn1, bn2, out_h, nq);
}

// round 11
// speedup vs baseline: 1.0964x; 1.0964x over previous
#include <cuda_runtime.h>
#include <cstdint>

#define NQ_CAP 20480          // 256 * 80 for the fused scan
#define E_CAP  640000
#define DF     128
#define LDA2   132            // padded row stride (words) -> conflict-free frags

// ---------------- static device scratch -------------------------------------
__device__ int      g_counts [NQ_CAP];
__device__ int      g_cursor [NQ_CAP];
__device__ int      g_eids   [E_CAP];
__device__ int      g_erow   [E_CAP];
__device__ float    g_agg    [(size_t)NQ_CAP * DF];
__device__ float    g_P      [(size_t)NQ_CAP * DF];   // h_q @ We1_top + b1
__device__ float    g_Q      [(size_t)NQ_CAP * DF];   // h_kv @ We1_bot
__device__ uint2    g_w1tp[8192];   // packed tf32 frag pairs: [ks][tg][n]
__device__ uint2    g_w1bp[8192];
__device__ uint2    g_w2ep[8192];
__device__ uint32_t g_w1n[256 * 128];
__device__ uint32_t g_w2n[128 * 128];
__device__ unsigned long long g_barv = 0;   // monotonic grid-barrier counter

// ---------------- helpers ---------------------------------------------------
__device__ __forceinline__ uint32_t f2tf(float x) {
    uint32_t u; asm("cvt.rna.tf32.f32 %0, %1;" : "=r"(u) : "f"(x)); return u;
}
__device__ __forceinline__ float silu(float x) {
    return __fdividef(x, 1.0f + __expf(-x));
}
__device__ __forceinline__ void mma8(float c[4], const uint32_t a[4],
                                     uint32_t b0, uint32_t b1) {
    asm("mma.sync.aligned.m16n8k8.row.col.f32.tf32.tf32.f32 "
        "{%0,%1,%2,%3}, {%4,%5,%6,%7}, {%8,%9}, {%0,%1,%2,%3};"
        : "+f"(c[0]), "+f"(c[1]), "+f"(c[2]), "+f"(c[3])
        : "r"(a[0]), "r"(a[1]), "r"(a[2]), "r"(a[3]), "r"(b0), "r"(b1));
}

// Monotonic-counter grid barrier (all blocks co-resident; graph-replay safe).
__device__ __forceinline__ void gbar(int nb) {
    __syncthreads();
    __threadfence();
    if (threadIdx.x == 0) {
        unsigned long long old = atomicAdd(&g_barv, 1ULL);
        unsigned long long target = (old / (unsigned long long)nb + 1ULL) *
                                    (unsigned long long)nb;
        unsigned long long v;
        do {
            asm volatile("ld.global.acquire.gpu.u64 %0, [%1];"
                         : "=l"(v) : "l"(&g_barv));
        } while (v < target);
    }
    __syncthreads();
}

// ---------------- fused CSR kernel: pack + zero + hist | scan | scatter -----
__global__ void __launch_bounds__(256, 1)
csr_kernel(const float* __restrict__ We1, const float* __restrict__ We2,
           const float* __restrict__ Wn1, const float* __restrict__ Wn2,
           const int* __restrict__ ei, int E, int nq) {
    int nb = gridDim.x;
    int gt = blockIdx.x * 256 + threadIdx.x;
    int gstride = nb * 256;

    for (int i = gt; i < 49152; i += gstride) {
        if (i < 8192) {
            int ks = i >> 9, tg = (i >> 7) & 3, n = i & 127;
            int k0 = ks * 8 + tg;
            g_w1tp[i] = make_uint2(f2tf(We1[k0 * 128 + n]),         f2tf(We1[(k0 + 4) * 128 + n]));
            g_w1bp[i] = make_uint2(f2tf(We1[(128 + k0) * 128 + n]), f2tf(We1[(132 + k0) * 128 + n]));
            g_w2ep[i] = make_uint2(f2tf(We2[k0 * 128 + n]),         f2tf(We2[(k0 + 4) * 128 + n]));
        }
        if (i < 32768) g_w1n[i] = f2tf(Wn1[i]);
        else           g_w2n[i - 32768] = f2tf(Wn2[i - 32768]);
    }
    for (int i = gt; i < NQ_CAP; i += gstride) g_counts[i] = 0;
    int nagg = nq * DF;
    for (int i = gt; i < nagg; i += gstride) g_agg[i] = 0.f;
    gbar(nb);
    for (int e = gt; e < E; e += gstride) atomicAdd(&g_counts[ei[e]], 1);
    gbar(nb);

    if (blockIdx.x == 0) {
        __shared__ int wt[8];
        int tid = threadIdx.x, lane = tid & 31, w = tid >> 5;
        int base = tid * 80;
        int s = 0;
        for (int i = 0; i < 80; i++) s += g_counts[base + i];
        int v = s;
#pragma unroll
        for (int o = 1; o < 32; o <<= 1) {
            int t = __shfl_up_sync(~0u, v, o); if (lane >= o) v += t;
        }
        if (lane == 31) wt[w] = v;
        __syncthreads();
        if (w == 0 && lane < 8) {
            int x = wt[lane];
#pragma unroll
            for (int o = 1; o < 8; o <<= 1) {
                int t = __shfl_up_sync(0xFFu, x, o); if (lane >= o) x += t;
            }
            wt[lane] = x;
        }
        __syncthreads();
        int ex = v + (w ? wt[w - 1] : 0) - s;
        for (int i = 0; i < 80; i++) {
            int c = g_counts[base + i];
            g_cursor[base + i] = ex;
            ex += c;
        }
    }
    gbar(nb);

    for (int e = gt; e < E; e += gstride) {
        int r = ei[e];
        int pos = atomicAdd(&g_cursor[r], 1);
        g_eids[pos] = e; g_erow[pos] = r;
    }
}

// ---------------- single-layer GEMM: P/Q precompute -------------------------
template <int SEL>
__global__ void __launch_bounds__(256, 2)
pq_kernel(const float* __restrict__ src, const float* __restrict__ bias, int nrows) {
    const uint2* __restrict__ Wp = (SEL == 0) ? g_w1tp : g_w1bp;
    float* __restrict__ dst      = (SEL == 0) ? g_P    : g_Q;
    extern __shared__ uint32_t As[];          // [128][LDA2]
    int tid = threadIdx.x;
    {
        int r = tid >> 1, half = tid & 1;
        int rowg = blockIdx.x * 128 + r;
        bool ok = rowg < nrows;
        const float4* s4 = (const float4*)(src + (size_t)(ok ? rowg : 0) * DF + half * 64);
#pragma unroll
        for (int j = 0; j < 16; j++) {
            float4 v = ok ? s4[j] : make_float4(0.f, 0.f, 0.f, 0.f);
            uint4 u; u.x = f2tf(v.x); u.y = f2tf(v.y); u.z = f2tf(v.z); u.w = f2tf(v.w);
            *(uint4*)&As[r * LDA2 + half * 64 + j * 4] = u;
        }
    }
    __syncthreads();

    int lane = tid & 31, wid = tid >> 5, gid = lane >> 2, tg = lane & 3;
    float acc[8][2][4];
#pragma unroll
    for (int nt = 0; nt < 2; nt++) {
        int col = wid * 16 + nt * 8 + tg * 2;
        float b0 = (SEL == 0) ? bias[col] : 0.f;
        float b1 = (SEL == 0) ? bias[col + 1] : 0.f;
#pragma unroll
        for (int mt = 0; mt < 8; mt++) {
            acc[mt][nt][0] = b0; acc[mt][nt][1] = b1;
            acc[mt][nt][2] = b0; acc[mt][nt][3] = b1;
        }
    }
#pragma unroll
    for (int ks = 0; ks < 16; ks++) {
        uint2 b0 = Wp[(ks * 4 + tg) * 128 + wid * 16 + gid];
        uint2 b1 = Wp[(ks * 4 + tg) * 128 + wid * 16 + 8 + gid];
#pragma unroll
        for (int mt = 0; mt < 8; mt++) {
            uint32_t a[4];
            const uint32_t* ap = As + (mt * 16 + gid) * LDA2 + ks * 8 + tg;
            a[0] = ap[0]; a[1] = ap[8 * LDA2]; a[2] = ap[4]; a[3] = ap[8 * LDA2 + 4];
            mma8(acc[mt][0], a, b0.x, b0.y);
            mma8(acc[mt][1], a, b1.x, b1.y);
        }
    }
#pragma unroll
    for (int mt = 0; mt < 8; mt++) {
        int r0 = blockIdx.x * 128 + mt * 16 + gid, r1 = r0 + 8;
#pragma unroll
        for (int nt = 0; nt < 2; nt++) {
            int col = wid * 16 + nt * 8 + tg * 2;
            if (r0 < nrows) {
                dst[(size_t)r0 * DF + col] = acc[mt][nt][0];
                dst[(size_t)r0 * DF + col + 1] = acc[mt][nt][1];
            }
            if (r1 < nrows) {
                dst[(size_t)r1 * DF + col] = acc[mt][nt][2];
                dst[(size_t)r1 * DF + col + 1] = acc[mt][nt][3];
            }
        }
    }
}

// ---------------- edge layer-2: 128-edge tiles, 2M x 4N warp grid -----------
// Warp tile 64 rows x 32 cols (mt=4, nt=4). H re-read factor 4x (was 8x).
#define SMEM_E ((128 * LDA2 + 256) * 4)

__global__ void __launch_bounds__(256, 2)
edge_l2_kernel(const int* __restrict__ ei, int E,
               const float* __restrict__ b2, float* __restrict__ out_m) {
    extern __shared__ uint32_t S[];
    uint32_t* As = S;                         // [128][LDA2] tf32 H tile
    float*    Rb = (float*)S;                 // reused fp32 out staging
    int* s_eid = (int*)(S + 128 * LDA2);
    int* s_row = (int*)(S + 128 * LDA2 + 128);
    int tid = threadIdx.x;

    // ---- gather & build H = silu(P[row] + Q[col]) as tf32 ----
    {
        int r = tid >> 1, half = tid & 1;     // 128 rows x 2 threads/row
        int ci = blockIdx.x * 128 + r;
        int eid = -1, row = 0, col = 0;
        if (ci < E) { eid = g_eids[ci]; row = g_erow[ci]; col = ei[E + eid]; }
        if (half == 0) { s_eid[r] = eid; s_row[r] = (eid >= 0) ? row : -1; }
        const float4* p4 = (const float4*)(g_P + (size_t)row * DF + half * 64);
        const float4* q4 = (const float4*)(g_Q + (size_t)col * DF + half * 64);
#pragma unroll
        for (int j = 0; j < 16; j++) {
            float4 p = (eid >= 0) ? p4[j] : make_float4(0.f, 0.f, 0.f, 0.f);
            float4 qq = (eid >= 0) ? q4[j] : make_float4(0.f, 0.f, 0.f, 0.f);
            uint4 u;
            u.x = f2tf(silu(p.x + qq.x)); u.y = f2tf(silu(p.y + qq.y));
            u.z = f2tf(silu(p.z + qq.z)); u.w = f2tf(silu(p.w + qq.w));
            *(uint4*)&As[r * LDA2 + half * 64 + j * 4] = u;
        }
    }
    __syncthreads();

    int lane = tid & 31, wid = tid >> 5, gid = lane >> 2, tg = lane & 3;
    int wm = wid >> 2, wn = wid & 3;          // 2 M-groups x 4 N-groups
    float acc[4][4][4];
#pragma unroll
    for (int nt = 0; nt < 4; nt++) {
        int col = wn * 32 + nt * 8 + tg * 2;
        float b0 = b2[col], b1 = b2[col + 1];
#pragma unroll
        for (int mt = 0; mt < 4; mt++) {
            acc[mt][nt][0] = b0; acc[mt][nt][1] = b1;
            acc[mt][nt][2] = b0; acc[mt][nt][3] = b1;
        }
    }
#pragma unroll
    for (int ks = 0; ks < 16; ks++) {
        uint2 bfr[4];
#pragma unroll
        for (int nt = 0; nt < 4; nt++)
            bfr[nt] = g_w2ep[(ks * 4 + tg) * 128 + wn * 32 + nt * 8 + gid];
#pragma unroll
        for (int mt = 0; mt < 4; mt++) {
            uint32_t a[4];
            const uint32_t* ap = As + (wm * 64 + mt * 16 + gid) * LDA2 + ks * 8 + tg;
            a[0] = ap[0]; a[1] = ap[8 * LDA2]; a[2] = ap[4]; a[3] = ap[8 * LDA2 + 4];
#pragma unroll
            for (int nt = 0; nt < 4; nt++)
                mma8(acc[mt][nt], a, bfr[nt].x, bfr[nt].y);
        }
    }
    __syncthreads();   // all warps done reading As -> safe to overwrite with Rb

    // ---- silu -> Rb (fp32) ----
#pragma unroll
    for (int mt = 0; mt < 4; mt++) {
        int r0 = wm * 64 + mt * 16 + gid, r1 = r0 + 8;
#pragma unroll
        for (int nt = 0; nt < 4; nt++) {
            int col = wn * 32 + nt * 8 + tg * 2;
            Rb[r0 * LDA2 + col]     = silu(acc[mt][nt][0]);
            Rb[r0 * LDA2 + col + 1] = silu(acc[mt][nt][1]);
            Rb[r1 * LDA2 + col]     = silu(acc[mt][nt][2]);
            Rb[r1 * LDA2 + col + 1] = silu(acc[mt][nt][3]);
        }
    }
    __syncthreads();

    // ---- coalesced mij store ----
#pragma unroll
    for (int rep = 0; rep < 16; rep++) {
        int i = tid + rep * 256;               // 4096 float4 = 128 rows x 32
        int row = i >> 5, c4 = i & 31;
        int eid = s_eid[row];
        if (eid >= 0)
            *(float4*)(out_m + (size_t)eid * DF + c4 * 4) = *(float4*)&Rb[row * LDA2 + c4 * 4];
    }

    // ---- fused segmented aggregation (CSR-sorted rows) ----
    {
        int col = tid & 127, half = tid >> 7;
        int cur = -1; float racc = 0.f;
#pragma unroll 4
        for (int r0 = 0; r0 < 64; r0++) {
            int r = half * 64 + r0;
            int rw = s_row[r];
            if (rw != cur) {
                if (cur >= 0) atomicAdd(&g_agg[(size_t)cur * DF + col], racc);
                cur = rw; racc = 0.f;
            }
            if (rw >= 0) racc += Rb[r * LDA2 + col];
        }
        if (cur >= 0) atomicAdd(&g_agg[(size_t)cur * DF + col], racc);
    }
}

// ---------------- node MLP (proven path) ------------------------------------
#define LDA 260
#define SMEM_N (128 * LDA * 4)

__device__ __forceinline__ void mma_tiles(const uint32_t* __restrict__ As,
                                          const uint32_t* __restrict__ Bw,
                                          int ksteps, float acc[2][8][4],
                                          int warp_m, int warp_n, int gid, int tg) {
    for (int ks = 0; ks < ksteps; ks++) {
        int k0 = ks * 8;
        uint32_t a[2][4];
#pragma unroll
        for (int mt = 0; mt < 2; mt++) {
            const uint32_t* ap = As + (warp_m * 32 + mt * 16 + gid) * LDA + k0 + tg;
            a[mt][0] = ap[0]; a[mt][1] = ap[8 * LDA];
            a[mt][2] = ap[4]; a[mt][3] = ap[8 * LDA + 4];
        }
#pragma unroll
        for (int nt = 0; nt < 8; nt++) {
            int n = warp_n * 64 + nt * 8 + gid;
            uint32_t b0 = Bw[(k0 + tg) * 128 + n];
            uint32_t b1 = Bw[(k0 + tg + 4) * 128 + n];
#pragma unroll
            for (int mt = 0; mt < 2; mt++) mma8(acc[mt][nt], a[mt], b0, b1);
        }
    }
}
__global__ void __launch_bounds__(256, 1)
node_kernel(const float* __restrict__ Aq,
            const float* __restrict__ bias1, const float* __restrict__ bias2,
            float* __restrict__ outp, int nrows) {
    extern __shared__ uint32_t As[];
    int tid = threadIdx.x;
    {
        int r = tid >> 1, half = tid & 1;
        int rowg = blockIdx.x * 128 + r;
        bool ok = rowg < nrows;
        int n = ok ? rowg : 0;
        const float4* src = half ? (const float4*)(g_agg + (size_t)n * DF)
                                 : (const float4*)(Aq + (size_t)n * DF);
#pragma unroll
        for (int j = 0; j < 32; j++) {
            float4 v = ok ? src[j] : make_float4(0.f, 0.f, 0.f, 0.f);
            uint4 u; u.x = f2tf(v.x); u.y = f2tf(v.y); u.z = f2tf(v.z); u.w = f2tf(v.w);
            *(uint4*)&As[r * LDA + (half * 32 + j) * 4] = u;
        }
    }
    __syncthreads();
    int lane = tid & 31, wid = tid >> 5;
    int warp_m = wid >> 1, warp_n = wid & 1;
    int gid = lane >> 2, tg = lane & 3;

    float acc[2][8][4];
#pragma unroll
    for (int nt = 0; nt < 8; nt++) {
        int col = warp_n * 64 + nt * 8 + tg * 2;
        float b0 = bias1[col], b1 = bias1[col + 1];
#pragma unroll
        for (int mt = 0; mt < 2; mt++) {
            acc[mt][nt][0] = b0; acc[mt][nt][1] = b1;
            acc[mt][nt][2] = b0; acc[mt][nt][3] = b1;
        }
    }
    mma_tiles(As, g_w1n, 32, acc, warp_m, warp_n, gid, tg);
    __syncthreads();
#pragma unroll
    for (int mt = 0; mt < 2; mt++) {
        int row = warp_m * 32 + mt * 16 + gid;
#pragma unroll
        for (int nt = 0; nt < 8; nt++) {
            int col = warp_n * 64 + nt * 8 + tg * 2;
            As[row * LDA + col]           = f2tf(silu(acc[mt][nt][0]));
            As[row * LDA + col + 1]       = f2tf(silu(acc[mt][nt][1]));
            As[(row + 8) * LDA + col]     = f2tf(silu(acc[mt][nt][2]));
            As[(row + 8) * LDA + col + 1] = f2tf(silu(acc[mt][nt][3]));
        }
    }
    __syncthreads();
#pragma unroll
    for (int nt = 0; nt < 8; nt++) {
        int col = warp_n * 64 + nt * 8 + tg * 2;
        float b0 = bias2[col], b1 = bias2[col + 1];
#pragma unroll
        for (int mt = 0; mt < 2; mt++) {
            acc[mt][nt][0] = b0; acc[mt][nt][1] = b1;
            acc[mt][nt][2] = b0; acc[mt][nt][3] = b1;
        }
    }
    mma_tiles(As, g_w2n, 16, acc, warp_m, warp_n, gid, tg);
#pragma unroll
    for (int mt = 0; mt < 2; mt++) {
        int row = warp_m * 32 + mt * 16 + gid;
        int rg0 = blockIdx.x * 128 + row, rg1 = rg0 + 8;
#pragma unroll
        for (int nt = 0; nt < 8; nt++) {
            int col = warp_n * 64 + nt * 8 + tg * 2;
            if (rg0 < nrows) {
                const float* h = Aq + (size_t)rg0 * DF + col;
                float* o = outp + (size_t)rg0 * DF + col;
                o[0] = acc[mt][nt][0] + h[0]; o[1] = acc[mt][nt][1] + h[1];
            }
            if (rg1 < nrows) {
                const float* h = Aq + (size_t)rg1 * DF + col;
                float* o = outp + (size_t)rg1 * DF + col;
                o[0] = acc[mt][nt][2] + h[0]; o[1] = acc[mt][nt][3] + h[1];
            }
        }
    }
}

// ---------------- launch ----------------------------------------------------
extern "C" void kernel_launch(void* const* d_in, const int* in_sizes, int n_in,
                              void* d_out, int out_size) {
    const float* h_q  = (const float*)d_in[0];
    const float* h_kv = (const float*)d_in[1];
    const int*   ei   = (const int*)d_in[2];
    const float* We1  = (const float*)d_in[3];
    const float* be1  = (const float*)d_in[4];
    const float* We2  = (const float*)d_in[5];
    const float* be2  = (const float*)d_in[6];
    const float* Wn1  = (const float*)d_in[7];
    const float* bn1  = (const float*)d_in[8];
    const float* Wn2  = (const float*)d_in[9];
    const float* bn2  = (const float*)d_in[10];

    int nq  = in_sizes[0] / DF;
    int nkv = in_sizes[1] / DF;
    int E   = in_sizes[2] / 2;

    float* out_h = (float*)d_out;
    float* out_m = (float*)d_out + (size_t)nq * DF;

    static int nsm = 0;
    if (!nsm) cudaDeviceGetAttribute(&nsm, cudaDevAttrMultiProcessorCount, 0);

    const int PQ_SMEM = 128 * LDA2 * 4;
    cudaFuncSetAttribute(pq_kernel<0>,   cudaFuncAttributeMaxDynamicSharedMemorySize, PQ_SMEM);
    cudaFuncSetAttribute(pq_kernel<1>,   cudaFuncAttributeMaxDynamicSharedMemorySize, PQ_SMEM);
    cudaFuncSetAttribute(edge_l2_kernel, cudaFuncAttributeMaxDynamicSharedMemorySize, SMEM_E);
    cudaFuncSetAttribute(node_kernel,    cudaFuncAttributeMaxDynamicSharedMemorySize, SMEM_N);

    // Launch order: csr(1), pq0(2), pq1(3), edge(4) <- ncu captures the 4th
    csr_kernel<<<nsm, 256>>>(We1, We2, Wn1, Wn2, ei, E, nq);
    pq_kernel<0><<<(nq + 127) / 128, 256, PQ_SMEM>>>(h_q, be1, nq);
    pq_kernel<1><<<(nkv + 127) / 128, 256, PQ_SMEM>>>(h_kv, be1, nkv);
    edge_l2_kernel<<<(E + 127) / 128, 256, SMEM_E>>>(ei, E, be2, out_m);
    node_kernel<<<(nq + 127) / 128, 256, SMEM_N>>>(h_q, bn1, bn2, out_h, nq);
}

// round 13
// speedup vs baseline: 1.1748x; 1.0715x over previous
#include <cuda_runtime.h>
#include <cstdint>

#define NQ_CAP 20480          // 256 * 80 for the fused scan
#define E_CAP  640000
#define DF     128
#define LDA2   132            // padded row stride (words) -> conflict-free frags

// ---------------- static device scratch -------------------------------------
__device__ int      g_counts [NQ_CAP];
__device__ int      g_cursor [NQ_CAP];
__device__ int      g_eids   [E_CAP];
__device__ int      g_erow   [E_CAP];
__device__ float    g_agg    [(size_t)NQ_CAP * DF];
__device__ float    g_P      [(size_t)NQ_CAP * DF];   // h_q @ We1_top + b1
__device__ float    g_Q      [(size_t)NQ_CAP * DF];   // h_kv @ We1_bot
__device__ uint2    g_w1tp[8192];   // packed tf32 frag pairs: [ks][tg][n]
__device__ uint2    g_w1bp[8192];
__device__ uint2    g_w2ep[8192];   // repacked: [kst][wn][gid][nt] for uint4 loads
__device__ uint32_t g_w1n[256 * 128];
__device__ uint32_t g_w2n[128 * 128];
__device__ unsigned long long g_barv = 0;   // monotonic grid-barrier counter

// ---------------- helpers ---------------------------------------------------
__device__ __forceinline__ uint32_t f2tf(float x) {
    uint32_t u; asm("cvt.rna.tf32.f32 %0, %1;" : "=r"(u) : "f"(x)); return u;
}
__device__ __forceinline__ float silu(float x) {
    return __fdividef(x, 1.0f + __expf(-x));
}
__device__ __forceinline__ void mma8(float c[4], const uint32_t a[4],
                                     uint32_t b0, uint32_t b1) {
    asm("mma.sync.aligned.m16n8k8.row.col.f32.tf32.tf32.f32 "
        "{%0,%1,%2,%3}, {%4,%5,%6,%7}, {%8,%9}, {%0,%1,%2,%3};"
        : "+f"(c[0]), "+f"(c[1]), "+f"(c[2]), "+f"(c[3])
        : "r"(a[0]), "r"(a[1]), "r"(a[2]), "r"(a[3]), "r"(b0), "r"(b1));
}

// Monotonic-counter grid barrier (all blocks co-resident; graph-replay safe).
__device__ __forceinline__ void gbar(int nb) {
    __syncthreads();
    __threadfence();
    if (threadIdx.x == 0) {
        unsigned long long old = atomicAdd(&g_barv, 1ULL);
        unsigned long long target = (old / (unsigned long long)nb + 1ULL) *
                                    (unsigned long long)nb;
        unsigned long long v;
        do {
            asm volatile("ld.global.acquire.gpu.u64 %0, [%1];"
                         : "=l"(v) : "l"(&g_barv));
        } while (v < target);
    }
    __syncthreads();
}

// ---------------- fused CSR kernel: pack + zero + hist | scan | scatter -----
__global__ void __launch_bounds__(256, 1)
csr_kernel(const float* __restrict__ We1, const float* __restrict__ We2,
           const float* __restrict__ Wn1, const float* __restrict__ Wn2,
           const int* __restrict__ ei, int E, int nq) {
    int nb = gridDim.x;
    int gt = blockIdx.x * 256 + threadIdx.x;
    int gstride = nb * 256;

    for (int i = gt; i < 49152; i += gstride) {
        if (i < 8192) {
            // w1tp/w1bp: [ks][tg][n] pair layout (n = 0..127)
            int ks = i >> 9, tg = (i >> 7) & 3, n = i & 127;
            int k0 = ks * 8 + tg;
            g_w1tp[i] = make_uint2(f2tf(We1[k0 * 128 + n]),         f2tf(We1[(k0 + 4) * 128 + n]));
            g_w1bp[i] = make_uint2(f2tf(We1[(128 + k0) * 128 + n]), f2tf(We1[(132 + k0) * 128 + n]));
            // w2ep: [kst][wn][gid][nt] so the 4 nt-frags are contiguous (2x uint4)
            int kst = i >> 7, rem = i & 127;
            int wn = rem >> 5, gid = (rem >> 2) & 7, nt = rem & 3;
            int n2 = wn * 32 + nt * 8 + gid;
            int ks2 = kst >> 2, tg2 = kst & 3;
            int k02 = ks2 * 8 + tg2;
            g_w2ep[i] = make_uint2(f2tf(We2[k02 * 128 + n2]), f2tf(We2[(k02 + 4) * 128 + n2]));
        }
        if (i < 32768) g_w1n[i] = f2tf(Wn1[i]);
        else           g_w2n[i - 32768] = f2tf(Wn2[i - 32768]);
    }
    for (int i = gt; i < NQ_CAP; i += gstride) g_counts[i] = 0;
    int nagg = nq * DF;
    for (int i = gt; i < nagg; i += gstride) g_agg[i] = 0.f;
    gbar(nb);
    for (int e = gt; e < E; e += gstride) atomicAdd(&g_counts[ei[e]], 1);
    gbar(nb);

    if (blockIdx.x == 0) {
        __shared__ int wt[8];
        int tid = threadIdx.x, lane = tid & 31, w = tid >> 5;
        int base = tid * 80;
        int s = 0;
        for (int i = 0; i < 80; i++) s += g_counts[base + i];
        int v = s;
#pragma unroll
        for (int o = 1; o < 32; o <<= 1) {
            int t = __shfl_up_sync(~0u, v, o); if (lane >= o) v += t;
        }
        if (lane == 31) wt[w] = v;
        __syncthreads();
        if (w == 0 && lane < 8) {
            int x = wt[lane];
#pragma unroll
            for (int o = 1; o < 8; o <<= 1) {
                int t = __shfl_up_sync(0xFFu, x, o); if (lane >= o) x += t;
            }
            wt[lane] = x;
        }
        __syncthreads();
        int ex = v + (w ? wt[w - 1] : 0) - s;
        for (int i = 0; i < 80; i++) {
            int c = g_counts[base + i];
            g_cursor[base + i] = ex;
            ex += c;
        }
    }
    gbar(nb);

    for (int e = gt; e < E; e += gstride) {
        int r = ei[e];
        int pos = atomicAdd(&g_cursor[r], 1);
        g_eids[pos] = e; g_erow[pos] = r;
    }
}

// ---------------- single-layer GEMM: P/Q precompute -------------------------
template <int SEL>
__global__ void __launch_bounds__(256, 2)
pq_kernel(const float* __restrict__ src, const float* __restrict__ bias, int nrows) {
    const uint2* __restrict__ Wp = (SEL == 0) ? g_w1tp : g_w1bp;
    float* __restrict__ dst      = (SEL == 0) ? g_P    : g_Q;
    extern __shared__ uint32_t As[];          // [128][LDA2]
    int tid = threadIdx.x;

    // ---- fully coalesced gather: 4096 float4 = 128 rows x 32 float4 ----
    {
        const float4* s4 = (const float4*)src;
        int rbase = blockIdx.x * 128;
#pragma unroll
        for (int t = 0; t < 16; t++) {
            int idx4 = tid + t * 256;
            int r = idx4 >> 5, w4 = idx4 & 31;
            bool ok = (rbase + r) < nrows;
            float4 v = ok ? s4[(size_t)(rbase + r) * 32 + w4]
                          : make_float4(0.f, 0.f, 0.f, 0.f);
            uint4 u; u.x = f2tf(v.x); u.y = f2tf(v.y); u.z = f2tf(v.z); u.w = f2tf(v.w);
            *(uint4*)&As[r * LDA2 + w4 * 4] = u;
        }
    }
    __syncthreads();

    int lane = tid & 31, wid = tid >> 5, gid = lane >> 2, tg = lane & 3;
    float acc[8][2][4];
#pragma unroll
    for (int nt = 0; nt < 2; nt++) {
        int col = wid * 16 + nt * 8 + tg * 2;
        float b0 = (SEL == 0) ? bias[col] : 0.f;
        float b1 = (SEL == 0) ? bias[col + 1] : 0.f;
#pragma unroll
        for (int mt = 0; mt < 8; mt++) {
            acc[mt][nt][0] = b0; acc[mt][nt][1] = b1;
            acc[mt][nt][2] = b0; acc[mt][nt][3] = b1;
        }
    }
#pragma unroll
    for (int ks = 0; ks < 16; ks++) {
        uint2 b0 = Wp[(ks * 4 + tg) * 128 + wid * 16 + gid];
        uint2 b1 = Wp[(ks * 4 + tg) * 128 + wid * 16 + 8 + gid];
#pragma unroll
        for (int mt = 0; mt < 8; mt++) {
            uint32_t a[4];
            const uint32_t* ap = As + (mt * 16 + gid) * LDA2 + ks * 8 + tg;
            a[0] = ap[0]; a[1] = ap[8 * LDA2]; a[2] = ap[4]; a[3] = ap[8 * LDA2 + 4];
            mma8(acc[mt][0], a, b0.x, b0.y);
            mma8(acc[mt][1], a, b1.x, b1.y);
        }
    }
#pragma unroll
    for (int mt = 0; mt < 8; mt++) {
        int r0 = blockIdx.x * 128 + mt * 16 + gid, r1 = r0 + 8;
#pragma unroll
        for (int nt = 0; nt < 2; nt++) {
            int col = wid * 16 + nt * 8 + tg * 2;
            if (r0 < nrows) {
                dst[(size_t)r0 * DF + col] = acc[mt][nt][0];
                dst[(size_t)r0 * DF + col + 1] = acc[mt][nt][1];
            }
            if (r1 < nrows) {
                dst[(size_t)r1 * DF + col] = acc[mt][nt][2];
                dst[(size_t)r1 * DF + col + 1] = acc[mt][nt][3];
            }
        }
    }
}

// ---------------- edge layer-2: 128-edge tiles, 2M x 4N warp grid -----------
#define SMEM_E ((128 * LDA2 + 256) * 4)

__global__ void __launch_bounds__(256, 2)
edge_l2_kernel(const int* __restrict__ ei, int E,
               const float* __restrict__ b2, float* __restrict__ out_m) {
    extern __shared__ uint32_t S[];
    uint32_t* As = S;                         // [128][LDA2] tf32 H tile
    float*    Rb = (float*)S;                 // reused fp32 out staging
    int* s_eid = (int*)(S + 128 * LDA2);
    int* s_row = (int*)(S + 128 * LDA2 + 128);
    int tid = threadIdx.x;
    int lane = tid & 31, wid = tid >> 5;

    // ---- gather H = silu(P[row] + Q[col]); warp = 2 rows, lane-contiguous --
    {
        int sub = lane & 15;                   // float4 slot within 256B half
#pragma unroll
        for (int pass = 0; pass < 8; pass++) {
            int r = pass * 16 + wid * 2 + (lane >> 4);
            int ci = blockIdx.x * 128 + r;
            int eid = -1, row = 0, col = 0;
            if (ci < E) { eid = g_eids[ci]; row = g_erow[ci]; col = ei[E + eid]; }
            if (sub == 0) { s_eid[r] = eid; s_row[r] = (eid >= 0) ? row : -1; }
            const float4* p4 = (const float4*)(g_P + (size_t)row * DF);
            const float4* q4 = (const float4*)(g_Q + (size_t)col * DF);
#pragma unroll
            for (int t = 0; t < 2; t++) {
                int w4 = sub + t * 16;         // float4 index 0..31
                float4 p = (eid >= 0) ? p4[w4] : make_float4(0.f, 0.f, 0.f, 0.f);
                float4 q = (eid >= 0) ? q4[w4] : make_float4(0.f, 0.f, 0.f, 0.f);
                uint4 u;
                u.x = f2tf(silu(p.x + q.x)); u.y = f2tf(silu(p.y + q.y));
                u.z = f2tf(silu(p.z + q.z)); u.w = f2tf(silu(p.w + q.w));
                *(uint4*)&As[r * LDA2 + w4 * 4] = u;
            }
        }
    }
    __syncthreads();

    int gid = lane >> 2, tg = lane & 3;
    int wm = wid >> 2, wn = wid & 3;          // 2 M-groups x 4 N-groups
    float acc[4][4][4];
#pragma unroll
    for (int nt = 0; nt < 4; nt++) {
        int col = wn * 32 + nt * 8 + tg * 2;
        float b0 = b2[col], b1 = b2[col + 1];
#pragma unroll
        for (int mt = 0; mt < 4; mt++) {
            acc[mt][nt][0] = b0; acc[mt][nt][1] = b1;
            acc[mt][nt][2] = b0; acc[mt][nt][3] = b1;
        }
    }
    const uint4* w2q = (const uint4*)g_w2ep;   // 2 uint2 frag-pairs per uint4
#pragma unroll
    for (int ks = 0; ks < 16; ks++) {
        uint4 bq0 = w2q[(ks * 4 + tg) * 64 + wn * 16 + gid * 2];      // nt0, nt1
        uint4 bq1 = w2q[(ks * 4 + tg) * 64 + wn * 16 + gid * 2 + 1];  // nt2, nt3
        uint2 bfr[4] = { make_uint2(bq0.x, bq0.y), make_uint2(bq0.z, bq0.w),
                         make_uint2(bq1.x, bq1.y), make_uint2(bq1.z, bq1.w) };
#pragma unroll
        for (int mt = 0; mt < 4; mt++) {
            uint32_t a[4];
            const uint32_t* ap = As + (wm * 64 + mt * 16 + gid) * LDA2 + ks * 8 + tg;
            a[0] = ap[0]; a[1] = ap[8 * LDA2]; a[2] = ap[4]; a[3] = ap[8 * LDA2 + 4];
#pragma unroll
            for (int nt = 0; nt < 4; nt++)
                mma8(acc[mt][nt], a, bfr[nt].x, bfr[nt].y);
        }
    }
    __syncthreads();   // all warps done reading As -> safe to overwrite with Rb

    // ---- silu -> Rb (fp32) ----
#pragma unroll
    for (int mt = 0; mt < 4; mt++) {
        int r0 = wm * 64 + mt * 16 + gid, r1 = r0 + 8;
#pragma unroll
        for (int nt = 0; nt < 4; nt++) {
            int col = wn * 32 + nt * 8 + tg * 2;
            Rb[r0 * LDA2 + col]     = silu(acc[mt][nt][0]);
            Rb[r0 * LDA2 + col + 1] = silu(acc[mt][nt][1]);
            Rb[r1 * LDA2 + col]     = silu(acc[mt][nt][2]);
            Rb[r1 * LDA2 + col + 1] = silu(acc[mt][nt][3]);
        }
    }
    __syncthreads();

    // ---- coalesced mij store ----
#pragma unroll
    for (int rep = 0; rep < 16; rep++) {
        int i = tid + rep * 256;               // 4096 float4 = 128 rows x 32
        int row = i >> 5, c4 = i & 31;
        int eid = s_eid[row];
        if (eid >= 0)
            *(float4*)(out_m + (size_t)eid * DF + c4 * 4) = *(float4*)&Rb[row * LDA2 + c4 * 4];
    }

    // ---- fused segmented aggregation (CSR-sorted rows) ----
    {
        int col = tid & 127, half = tid >> 7;
        int cur = -1; float racc = 0.f;
#pragma unroll 4
        for (int r0 = 0; r0 < 64; r0++) {
            int r = half * 64 + r0;
            int rw = s_row[r];
            if (rw != cur) {
                if (cur >= 0) atomicAdd(&g_agg[(size_t)cur * DF + col], racc);
                cur = rw; racc = 0.f;
            }
            if (rw >= 0) racc += Rb[r * LDA2 + col];
        }
        if (cur >= 0) atomicAdd(&g_agg[(size_t)cur * DF + col], racc);
    }
}

// ---------------- node MLP ---------------------------------------------------
#define LDA 260
#define SMEM_N (128 * LDA * 4)

__device__ __forceinline__ void mma_tiles(const uint32_t* __restrict__ As,
                                          const uint32_t* __restrict__ Bw,
                                          int ksteps, float acc[2][8][4],
                                          int warp_m, int warp_n, int gid, int tg) {
    for (int ks = 0; ks < ksteps; ks++) {
        int k0 = ks * 8;
        uint32_t a[2][4];
#pragma unroll
        for (int mt = 0; mt < 2; mt++) {
            const uint32_t* ap = As + (warp_m * 32 + mt * 16 + gid) * LDA + k0 + tg;
            a[mt][0] = ap[0]; a[mt][1] = ap[8 * LDA];
            a[mt][2] = ap[4]; a[mt][3] = ap[8 * LDA + 4];
        }
#pragma unroll
        for (int nt = 0; nt < 8; nt++) {
            int n = warp_n * 64 + nt * 8 + gid;
            uint32_t b0 = Bw[(k0 + tg) * 128 + n];
            uint32_t b1 = Bw[(k0 + tg + 4) * 128 + n];
#pragma unroll
            for (int mt = 0; mt < 2; mt++) mma8(acc[mt][nt], a[mt], b0, b1);
        }
    }
}
__global__ void __launch_bounds__(256, 1)
node_kernel(const float* __restrict__ Aq,
            const float* __restrict__ bias1, const float* __restrict__ bias2,
            float* __restrict__ outp, int nrows) {
    extern __shared__ uint32_t As[];
    int tid = threadIdx.x;

    // ---- coalesced gather: row = [h_q[n] (words 0..127) | agg[n] (128..255)] --
    {
        const float4* a4 = (const float4*)Aq;
        const float4* g4 = (const float4*)g_agg;
        int rbase = blockIdx.x * 128;
#pragma unroll
        for (int t = 0; t < 32; t++) {
            int idx4 = tid + t * 256;          // 8192 float4 = 128 rows x 64
            int r = idx4 >> 6, part = (idx4 >> 5) & 1, w4 = idx4 & 31;
            bool ok = (rbase + r) < nrows;
            size_t si = (size_t)(rbase + r) * 32 + w4;
            float4 v = ok ? (part ? g4[si] : a4[si]) : make_float4(0.f, 0.f, 0.f, 0.f);
            uint4 u; u.x = f2tf(v.x); u.y = f2tf(v.y); u.z = f2tf(v.z); u.w = f2tf(v.w);
            *(uint4*)&As[r * LDA + (part * 32 + w4) * 4] = u;
        }
    }
    __syncthreads();
    int lane = tid & 31, wid = tid >> 5;
    int warp_m = wid >> 1, warp_n = wid & 1;
    int gid = lane >> 2, tg = lane & 3;

    float acc[2][8][4];
#pragma unroll
    for (int nt = 0; nt < 8; nt++) {
        int col = warp_n * 64 + nt * 8 + tg * 2;
        float b0 = bias1[col], b1 = bias1[col + 1];
#pragma unroll
        for (int mt = 0; mt < 2; mt++) {
            acc[mt][nt][0] = b0; acc[mt][nt][1] = b1;
            acc[mt][nt][2] = b0; acc[mt][nt][3] = b1;
        }
    }
    mma_tiles(As, g_w1n, 32, acc, warp_m, warp_n, gid, tg);
    __syncthreads();
#pragma unroll
    for (int mt = 0; mt < 2; mt++) {
        int row = warp_m * 32 + mt * 16 + gid;
#pragma unroll
        for (int nt = 0; nt < 8; nt++) {
            int col = warp_n * 64 + nt * 8 + tg * 2;
            As[row * LDA + col]           = f2tf(silu(acc[mt][nt][0]));
            As[row * LDA + col + 1]       = f2tf(silu(acc[mt][nt][1]));
            As[(row + 8) * LDA + col]     = f2tf(silu(acc[mt][nt][2]));
            As[(row + 8) * LDA + col + 1] = f2tf(silu(acc[mt][nt][3]));
        }
    }
    __syncthreads();
#pragma unroll
    for (int nt = 0; nt < 8; nt++) {
        int col = warp_n * 64 + nt * 8 + tg * 2;
        float b0 = bias2[col], b1 = bias2[col + 1];
#pragma unroll
        for (int mt = 0; mt < 2; mt++) {
            acc[mt][nt][0] = b0; acc[mt][nt][1] = b1;
            acc[mt][nt][2] = b0; acc[mt][nt][3] = b1;
        }
    }
    mma_tiles(As, g_w2n, 16, acc, warp_m, warp_n, gid, tg);
#pragma unroll
    for (int mt = 0; mt < 2; mt++) {
        int row = warp_m * 32 + mt * 16 + gid;
        int rg0 = blockIdx.x * 128 + row, rg1 = rg0 + 8;
#pragma unroll
        for (int nt = 0; nt < 8; nt++) {
            int col = warp_n * 64 + nt * 8 + tg * 2;
            if (rg0 < nrows) {
                const float* h = Aq + (size_t)rg0 * DF + col;
                float* o = outp + (size_t)rg0 * DF + col;
                o[0] = acc[mt][nt][0] + h[0]; o[1] = acc[mt][nt][1] + h[1];
            }
            if (rg1 < nrows) {
                const float* h = Aq + (size_t)rg1 * DF + col;
                float* o = outp + (size_t)rg1 * DF + col;
                o[0] = acc[mt][nt][2] + h[0]; o[1] = acc[mt][nt][3] + h[1];
            }
        }
    }
}

// ---------------- launch ----------------------------------------------------
extern "C" void kernel_launch(void* const* d_in, const int* in_sizes, int n_in,
                              void* d_out, int out_size) {
    const float* h_q  = (const float*)d_in[0];
    const float* h_kv = (const float*)d_in[1];
    const int*   ei   = (const int*)d_in[2];
    const float* We1  = (const float*)d_in[3];
    const float* be1  = (const float*)d_in[4];
    const float* We2  = (const float*)d_in[5];
    const float* be2  = (const float*)d_in[6];
    const float* Wn1  = (const float*)d_in[7];
    const float* bn1  = (const float*)d_in[8];
    const float* Wn2  = (const float*)d_in[9];
    const float* bn2  = (const float*)d_in[10];

    int nq  = in_sizes[0] / DF;
    int nkv = in_sizes[1] / DF;
    int E   = in_sizes[2] / 2;

    float* out_h = (float*)d_out;
    float* out_m = (float*)d_out + (size_t)nq * DF;

    static int nsm = 0;
    if (!nsm) cudaDeviceGetAttribute(&nsm, cudaDevAttrMultiProcessorCount, 0);

    const int PQ_SMEM = 128 * LDA2 * 4;
    cudaFuncSetAttribute(pq_kernel<0>,   cudaFuncAttributeMaxDynamicSharedMemorySize, PQ_SMEM);
    cudaFuncSetAttribute(pq_kernel<1>,   cudaFuncAttributeMaxDynamicSharedMemorySize, PQ_SMEM);
    cudaFuncSetAttribute(edge_l2_kernel, cudaFuncAttributeMaxDynamicSharedMemorySize, SMEM_E);
    cudaFuncSetAttribute(node_kernel,    cudaFuncAttributeMaxDynamicSharedMemorySize, SMEM_N);

    // Launch order: csr(1), pq0(2), pq1(3), edge(4) <- ncu captures the 4th
    csr_kernel<<<nsm, 256>>>(We1, We2, Wn1, Wn2, ei, E, nq);
    pq_kernel<0><<<(nq + 127) / 128, 256, PQ_SMEM>>>(h_q, be1, nq);
    pq_kernel<1><<<(nkv + 127) / 128, 256, PQ_SMEM>>>(h_kv, be1, nkv);
    edge_l2_kernel<<<(E + 127) / 128, 256, SMEM_E>>>(ei, E, be2, out_m);
    node_kernel<<<(nq + 127) / 128, 256, SMEM_N>>>(h_q, bn1, bn2, out_h, nq);
}